// round 16
// baseline (speedup 1.0000x reference)
#include <cuda_runtime.h>
#include <cuda_fp16.h>
#include <cstdint>

#define NSRC0 100000
#define NDST0 20000
#define NDST1 5000
#define NE0   160000
#define NE1   40000
#define IN_F  512
#define H_F   1024
#define N_CLS 256

#define APAD 40   // fp16 elems per smem row (32 data + 8 pad) -> 80B stride

// ---------------------------------------------------------------------------
// Scratch (device globals)
// ---------------------------------------------------------------------------
__device__ __align__(16) __half g_x16[(long long)NDST0 * IN_F];
__device__ __align__(16) __half g_a1[(long long)NDST0 * IN_F];
__device__ __align__(16) __half g_h16[(long long)NDST0 * H_F];
__device__ __align__(16) __half g_a2[(long long)NDST1 * H_F];

__device__ int g_cnt0[NDST0];
__device__ int g_off0[NDST0 + 1];
__device__ int g_cur0[NDST0];
__device__ int g_eidx0[NE0];
__device__ int g_cnt1[NDST1];
__device__ int g_off1[NDST1 + 1];
__device__ int g_cur1[NDST1];
__device__ int g_eidx1[NE1];

// fp16-rounded, pre-transposed weights: [N, K]
__device__ __align__(16) __half g_w1s[H_F * IN_F];
__device__ __align__(16) __half g_w1n[H_F * IN_F];
__device__ __align__(16) __half g_w2s[N_CLS * H_F];
__device__ __align__(16) __half g_w2n[N_CLS * H_F];

// ---------------------------------------------------------------------------
// helpers
// ---------------------------------------------------------------------------
__device__ __forceinline__ void cp16(uint32_t dst, const void* src, bool pred) {
    asm volatile("cp.async.cg.shared.global [%0], [%1], 16, %2;"
                 :: "r"(dst), "l"(src), "r"(pred ? 16 : 0));
}
__device__ __forceinline__ uint32_t pack2h(float x, float y) {
    __half hx = __float2half_rn(x);
    __half hy = __float2half_rn(y);
    return ((uint32_t)__half_as_ushort(hy) << 16) | __half_as_ushort(hx);
}
__device__ __forceinline__ void mma16816(float* c, const uint32_t* a,
                                         uint32_t b0, uint32_t b1) {
    asm volatile(
        "mma.sync.aligned.m16n8k16.row.col.f32.f16.f16.f32 "
        "{%0,%1,%2,%3}, {%4,%5,%6,%7}, {%8,%9}, {%0,%1,%2,%3};"
        : "+f"(c[0]), "+f"(c[1]), "+f"(c[2]), "+f"(c[3])
        : "r"(a[0]), "r"(a[1]), "r"(a[2]), "r"(a[3]), "r"(b0), "r"(b1));
}
#define LDSM4(r0, r1, r2, r3, addr) \
    asm volatile("ldmatrix.sync.aligned.m8n8.x4.shared.b16 {%0,%1,%2,%3}, [%4];" \
                 : "=r"(r0), "=r"(r1), "=r"(r2), "=r"(r3) : "r"(addr))

// ---------------------------------------------------------------------------
// Prep (side stream): 4 weight transposes (fp16 round) + x fp16 round.
// ---------------------------------------------------------------------------
__device__ __forceinline__ void transpose_round_body(
    const float* __restrict__ W, __half* __restrict__ dst,
    int K, int N, int n0, int k0) {
    __shared__ float t[32][33];
    int tx = threadIdx.x, ty = threadIdx.y;
#pragma unroll
    for (int i = 0; i < 4; i++)
        t[ty + 8 * i][tx] = W[(long long)(k0 + ty + 8 * i) * N + n0 + tx];
    __syncthreads();
#pragma unroll
    for (int i = 0; i < 4; i++) {
        float v = t[tx][ty + 8 * i];
        dst[(long long)(n0 + ty + 8 * i) * K + k0 + tx] = __float2half_rn(v);
    }
}

#define PREP_XSPLIT_BASE 1536
#define PREP_XSPLIT_BLKS 10000
#define PREP_TOTAL_BLKS  (PREP_XSPLIT_BASE + PREP_XSPLIT_BLKS)

__global__ void prep_all_kernel(const float* __restrict__ W1s, const float* __restrict__ W1n,
                                const float* __restrict__ W2s, const float* __restrict__ W2n,
                                const float* __restrict__ x) {
    int b = blockIdx.x;
    int flat = threadIdx.y * 32 + threadIdx.x;
    if (b < 1024) {
        int bb = b & 511;
        const float* W = (b < 512) ? W1s : W1n;
        __half* dst = (b < 512) ? g_w1s : g_w1n;
        transpose_round_body(W, dst, IN_F, H_F, (bb & 31) * 32, (bb >> 5) * 32);
    } else if (b < PREP_XSPLIT_BASE) {
        int bb = (b - 1024) & 255;
        const float* W = (b < 1280) ? W2s : W2n;
        __half* dst = (b < 1280) ? g_w2s : g_w2n;
        transpose_round_body(W, dst, H_F, N_CLS, (bb & 7) * 32, (bb >> 3) * 32);
    } else {
        long long i = (long long)(b - PREP_XSPLIT_BASE) * 256 + flat;
        const long long n4 = (long long)NDST0 * IN_F / 4;
        if (i < n4) {
            float4 v = reinterpret_cast<const float4*>(x)[i];
            reinterpret_cast<uint2*>(g_x16)[i] =
                make_uint2(pack2h(v.x, v.y), pack2h(v.z, v.w));
        }
    }
}

// ---------------------------------------------------------------------------
// CSR build (main stream)
// ---------------------------------------------------------------------------
__global__ void zero_counts_kernel() {
    int i = blockIdx.x * blockDim.x + threadIdx.x;
    if (i < NDST0) g_cnt0[i] = 0;
    if (i < NDST1) g_cnt1[i] = 0;
}
__global__ void count_both_kernel(const int* __restrict__ e0dst,
                                  const int* __restrict__ e1dst) {
    int e = blockIdx.x * blockDim.x + threadIdx.x;
    if (e < NE0) atomicAdd(&g_cnt0[e0dst[e]], 1);
    else if (e < NE0 + NE1) atomicAdd(&g_cnt1[e1dst[e - NE0]], 1);
}
__global__ void __launch_bounds__(1024) scan_kernel() {
    const int n = blockIdx.x == 0 ? NDST0 : NDST1;
    int* cnt = blockIdx.x == 0 ? g_cnt0 : g_cnt1;
    int* off = blockIdx.x == 0 ? g_off0 : g_off1;
    int* cur = blockIdx.x == 0 ? g_cur0 : g_cur1;
    __shared__ int wsum[32];
    int tid = threadIdx.x;
    int lane = tid & 31, wid = tid >> 5;
    int chunk = (n + 1023) >> 10;
    int beg = tid * chunk, end = min(beg + chunk, n);
    int s = 0;
    for (int i = beg; i < end; i++) s += cnt[i];
    int sc = s;
#pragma unroll
    for (int d = 1; d < 32; d <<= 1) {
        int v = __shfl_up_sync(0xFFFFFFFF, sc, d);
        if (lane >= d) sc += v;
    }
    if (lane == 31) wsum[wid] = sc;
    __syncthreads();
    if (wid == 0) {
        int v = wsum[lane];
#pragma unroll
        for (int d = 1; d < 32; d <<= 1) {
            int u = __shfl_up_sync(0xFFFFFFFF, v, d);
            if (lane >= d) v += u;
        }
        wsum[lane] = v;
    }
    __syncthreads();
    int prefix = (wid ? wsum[wid - 1] : 0) + sc - s;   // exclusive
    for (int i = beg; i < end; i++) {
        off[i] = prefix;
        cur[i] = prefix;
        prefix += cnt[i];
    }
    if (tid == 1023) off[n] = prefix;
}
__global__ void fill_both_kernel(const int* __restrict__ e0src, const int* __restrict__ e0dst,
                                 const int* __restrict__ e1src, const int* __restrict__ e1dst) {
    int e = blockIdx.x * blockDim.x + threadIdx.x;
    if (e < NE0) {
        int p = atomicAdd(&g_cur0[e0dst[e]], 1);
        g_eidx0[p] = e0src[e];
    } else if (e < NE0 + NE1) {
        int i = e - NE0;
        int p = atomicAdd(&g_cur1[e1dst[i]], 1);
        g_eidx1[p] = e1src[i];
    }
}

// ---------------------------------------------------------------------------
// Gather-mean + fp16 round: fp32 source (layer 1)
// ---------------------------------------------------------------------------
template <int F>
__global__ void __launch_bounds__(F / 4)
gather_mean_round_f32(const float* __restrict__ feat,
                      const int* __restrict__ off, const int* __restrict__ eidx,
                      __half* __restrict__ dst) {
    int row = blockIdx.x;
    int tid = threadIdx.x;
    int beg = off[row], end = off[row + 1];
    float4 acc = make_float4(0.f, 0.f, 0.f, 0.f);
    int j = beg;
    for (; j + 2 <= end; j += 2) {
        int s0 = eidx[j], s1 = eidx[j + 1];
        float4 v0 = reinterpret_cast<const float4*>(feat)[(long long)s0 * (F / 4) + tid];
        float4 v1 = reinterpret_cast<const float4*>(feat)[(long long)s1 * (F / 4) + tid];
        acc.x += v0.x + v1.x; acc.y += v0.y + v1.y;
        acc.z += v0.z + v1.z; acc.w += v0.w + v1.w;
    }
    if (j < end) {
        float4 v = reinterpret_cast<const float4*>(feat)[(long long)eidx[j] * (F / 4) + tid];
        acc.x += v.x; acc.y += v.y; acc.z += v.z; acc.w += v.w;
    }
    float sc = 1.0f / (float)max(end - beg, 1);
    acc.x *= sc; acc.y *= sc; acc.z *= sc; acc.w *= sc;
    long long o = (long long)row * (F / 4) + tid;
    reinterpret_cast<uint2*>(dst)[o] =
        make_uint2(pack2h(acc.x, acc.y), pack2h(acc.z, acc.w));
}

// ---------------------------------------------------------------------------
// Gather-mean + fp16 round: fp16 source (layer 2)
// ---------------------------------------------------------------------------
template <int F>
__global__ void __launch_bounds__(F / 4)
gather_mean_round_f16(const __half* __restrict__ feat,
                      const int* __restrict__ off, const int* __restrict__ eidx,
                      __half* __restrict__ dst) {
    int row = blockIdx.x;
    int tid = threadIdx.x;
    int beg = off[row], end = off[row + 1];
    float4 acc = make_float4(0.f, 0.f, 0.f, 0.f);
    int j = beg;
    for (; j + 2 <= end; j += 2) {
        int s0 = eidx[j], s1 = eidx[j + 1];
        uint2 u0 = reinterpret_cast<const uint2*>(feat)[(long long)s0 * (F / 4) + tid];
        uint2 u1 = reinterpret_cast<const uint2*>(feat)[(long long)s1 * (F / 4) + tid];
        float2 a0 = __half22float2(*reinterpret_cast<__half2*>(&u0.x));
        float2 b0 = __half22float2(*reinterpret_cast<__half2*>(&u0.y));
        float2 a1 = __half22float2(*reinterpret_cast<__half2*>(&u1.x));
        float2 b1 = __half22float2(*reinterpret_cast<__half2*>(&u1.y));
        acc.x += a0.x + a1.x; acc.y += a0.y + a1.y;
        acc.z += b0.x + b1.x; acc.w += b0.y + b1.y;
    }
    if (j < end) {
        uint2 u = reinterpret_cast<const uint2*>(feat)[(long long)eidx[j] * (F / 4) + tid];
        float2 a = __half22float2(*reinterpret_cast<__half2*>(&u.x));
        float2 b = __half22float2(*reinterpret_cast<__half2*>(&u.y));
        acc.x += a.x; acc.y += a.y; acc.z += b.x; acc.w += b.y;
    }
    float sc = 1.0f / (float)max(end - beg, 1);
    acc.x *= sc; acc.y *= sc; acc.z *= sc; acc.w *= sc;
    long long o = (long long)row * (F / 4) + tid;
    reinterpret_cast<uint2*>(dst)[o] =
        make_uint2(pack2h(acc.x, acc.y), pack2h(acc.z, acc.w));
}

// ---------------------------------------------------------------------------
// 2-stage BK=32 pipelined dual-pair plain-fp16 GEMM:
//   C/C16 = act( A0 @ B0^T + A1 @ B1^T + bias )
// ---------------------------------------------------------------------------
template <int NW_N>
__global__ void __launch_bounds__(256, 2)
sage_mma_gemm(const __half* __restrict__ A0, const __half* __restrict__ A1,
              const __half* __restrict__ B0, const __half* __restrict__ B1,
              const float* __restrict__ bias, float* __restrict__ C,
              __half* __restrict__ C16,
              int M, int N, int K, int doRelu) {
    constexpr int BM = 32 * (8 / NW_N);      // 128 | 64
    constexpr int NJ = 128 / (8 * NW_N);     // 8 | 4
    constexpr int NA = BM / 64;              // 2 | 1
    constexpr int ATILE = BM * APAD;
    constexpr int BTILE = 128 * APAD;
    constexpr int SSTRIDE = ATILE + BTILE;

    extern __shared__ __half sm[];
    uint32_t sbase = (uint32_t)__cvta_generic_to_shared(sm);

    int tid = threadIdx.x;
    int wid = tid >> 5;
    int lane = tid & 31;
    int g = lane >> 2;
    int t = lane & 3;
    int warpM = wid / NW_N;
    int warpN = wid % NW_N;
    int rowC = blockIdx.y * BM;
    int colC = blockIdx.x * 128;

    const uint32_t offA = ((uint32_t)(((lane & 15) + warpM * 32) * APAD
                          + ((lane >> 4) << 3))) * 2;
    const uint32_t offBl = ((uint32_t)((((lane >> 4) << 3) + (lane & 7)) * APAD
                          + (((lane >> 3) & 1) << 3))) * 2;

    long long offAg[NA];
    uint32_t  smA[NA];
    bool      pv[NA];
#pragma unroll
    for (int it = 0; it < NA; it++) {
        int u = tid + it * 256;
        int r = u >> 2, c = u & 3;
        int gr = rowC + r;
        pv[it] = gr < M;
        offAg[it] = (long long)(pv[it] ? gr : 0) * K + (c << 3);
        smA[it] = (uint32_t)(r * APAD + (c << 3)) * 2;
    }
    long long offBg[2];
    uint32_t  smB[2];
#pragma unroll
    for (int it = 0; it < 2; it++) {
        int u = tid + it * 256;
        int r = u >> 2, c = u & 3;
        offBg[it] = (long long)(colC + r) * K + (c << 3);
        smB[it] = (uint32_t)(r * APAD + (c << 3)) * 2;
    }

    const int nk = K >> 5;
    const int total = 2 * nk;

    auto issue = [&](int q, int s) {
        int pass = q >= nk;
        int k0 = (pass ? q - nk : q) << 5;
        const __half* Ap = pass ? A1 : A0;
        const __half* Bp = pass ? B1 : B0;
        uint32_t sb = sbase + (uint32_t)s * (SSTRIDE * 2);
#pragma unroll
        for (int it = 0; it < NA; it++)
            cp16(sb + smA[it], Ap + offAg[it] + k0, pv[it]);
#pragma unroll
        for (int it = 0; it < 2; it++)
            cp16(sb + ATILE * 2 + smB[it], Bp + offBg[it] + k0, true);
        asm volatile("cp.async.commit_group;" ::: "memory");
    };

    float acc[2][NJ][4];
#pragma unroll
    for (int i = 0; i < 2; i++)
#pragma unroll
        for (int j = 0; j < NJ; j++)
#pragma unroll
            for (int q = 0; q < 4; q++) acc[i][j][q] = 0.0f;

    issue(0, 0);

#pragma unroll 1
    for (int q = 0; q < total; q++) {
        int s = q & 1;
        if (q + 1 < total) {
            issue(q + 1, s ^ 1);
            asm volatile("cp.async.wait_group 1;" ::: "memory");
        } else {
            asm volatile("cp.async.wait_group 0;" ::: "memory");
        }
        __syncthreads();

        uint32_t baseA = sbase + (uint32_t)s * (SSTRIDE * 2);
        uint32_t baseB = baseA + ATILE * 2;

#pragma unroll
        for (int ks = 0; ks < 2; ks++) {
            uint32_t kof = (uint32_t)ks * 32;
            uint32_t ah[2][4];
#pragma unroll
            for (int i = 0; i < 2; i++)
                LDSM4(ah[i][0], ah[i][1], ah[i][2], ah[i][3],
                      baseA + offA + (uint32_t)(i * 16 * APAD) * 2 + kof);
            uint32_t b[NJ][2];
#pragma unroll
            for (int j2 = 0; j2 < NJ / 2; j2++) {
                uint32_t nbo = (uint32_t)((warpN * (NJ * 8) + j2 * 16) * APAD) * 2;
                LDSM4(b[2 * j2][0], b[2 * j2][1], b[2 * j2 + 1][0], b[2 * j2 + 1][1],
                      baseB + offBl + nbo + kof);
            }
#pragma unroll
            for (int i = 0; i < 2; i++)
#pragma unroll
                for (int j = 0; j < NJ; j++)
                    mma16816(acc[i][j], ah[i], b[j][0], b[j][1]);
        }
        __syncthreads();
    }

    // epilogue
#pragma unroll
    for (int i = 0; i < 2; i++) {
#pragma unroll
        for (int j = 0; j < NJ; j++) {
            int row = rowC + warpM * 32 + i * 16 + g;
            int col = colC + warpN * (NJ * 8) + j * 8 + 2 * t;
            float bx = bias[col], by = bias[col + 1];
            float2 v0, v1;
            v0.x = acc[i][j][0] + bx; v0.y = acc[i][j][1] + by;
            v1.x = acc[i][j][2] + bx; v1.y = acc[i][j][3] + by;
            if (doRelu) {
                v0.x = fmaxf(v0.x, 0.f); v0.y = fmaxf(v0.y, 0.f);
                v1.x = fmaxf(v1.x, 0.f); v1.y = fmaxf(v1.y, 0.f);
            }
            if (C) {
                if (row < M)
                    *reinterpret_cast<float2*>(C + (long long)row * N + col) = v0;
                if (row + 8 < M)
                    *reinterpret_cast<float2*>(C + (long long)(row + 8) * N + col) = v1;
            }
            if (C16) {
                if (row < M)
                    *reinterpret_cast<uint32_t*>(C16 + (long long)row * N + col) =
                        pack2h(v0.x, v0.y);
                if (row + 8 < M)
                    *reinterpret_cast<uint32_t*>(C16 + (long long)(row + 8) * N + col) =
                        pack2h(v1.x, v1.y);
            }
        }
    }
}

// ---------------------------------------------------------------------------
extern "C" void kernel_launch(void* const* d_in, const int* in_sizes, int n_in,
                              void* d_out, int out_size) {
    const float* x        = (const float*)d_in[0];
    const float* W_self1  = (const float*)d_in[1];
    const float* W_neigh1 = (const float*)d_in[2];
    const float* b1       = (const float*)d_in[3];
    const float* W_self2  = (const float*)d_in[4];
    const float* W_neigh2 = (const float*)d_in[5];
    const float* b2       = (const float*)d_in[6];
    const int*   e0_src   = (const int*)d_in[7];
    const int*   e0_dst   = (const int*)d_in[8];
    const int*   e1_src   = (const int*)d_in[9];
    const int*   e1_dst   = (const int*)d_in[10];
    float* out = (float*)d_out;

    __half *x16, *a1, *h16, *a2;
    cudaGetSymbolAddress((void**)&x16, g_x16);
    cudaGetSymbolAddress((void**)&a1,  g_a1);
    cudaGetSymbolAddress((void**)&h16, g_h16);
    cudaGetSymbolAddress((void**)&a2,  g_a2);
    __half *w1s, *w1n, *w2s, *w2n;
    cudaGetSymbolAddress((void**)&w1s, g_w1s);
    cudaGetSymbolAddress((void**)&w1n, g_w1n);
    cudaGetSymbolAddress((void**)&w2s, g_w2s);
    cudaGetSymbolAddress((void**)&w2n, g_w2n);
    int *off0, *eidx0, *off1, *eidx1;
    cudaGetSymbolAddress((void**)&off0, g_off0);
    cudaGetSymbolAddress((void**)&eidx0, g_eidx0);
    cudaGetSymbolAddress((void**)&off1, g_off1);
    cudaGetSymbolAddress((void**)&eidx1, g_eidx1);

    constexpr int SMEM1 = 2 * ((128 + 128) * APAD * 2);  // 40960B
    constexpr int SMEM2 = 2 * ((64 + 128) * APAD * 2);   // 30720B

    static cudaStream_t s1 = nullptr;
    static cudaEvent_t evFork = nullptr, evPrep = nullptr;
    static bool init_done = false;
    if (!init_done) {
        cudaFuncSetAttribute(sage_mma_gemm<2>, cudaFuncAttributeMaxDynamicSharedMemorySize, SMEM1);
        cudaFuncSetAttribute(sage_mma_gemm<4>, cudaFuncAttributeMaxDynamicSharedMemorySize, SMEM2);
        cudaStreamCreateWithFlags(&s1, cudaStreamNonBlocking);
        cudaEventCreateWithFlags(&evFork, cudaEventDisableTiming);
        cudaEventCreateWithFlags(&evPrep, cudaEventDisableTiming);
        init_done = true;
    }

    // ---- fork: prep (weights + x16) on side stream ----
    cudaEventRecord(evFork, 0);
    cudaStreamWaitEvent(s1, evFork, 0);
    prep_all_kernel<<<PREP_TOTAL_BLKS, dim3(32, 8), 0, s1>>>(
        W_self1, W_neigh1, W_self2, W_neigh2, x);
    cudaEventRecord(evPrep, s1);

    // ---- main stream: CSR chain + gather1 (independent of prep) ----
    zero_counts_kernel<<<(NDST0 + 255) / 256, 256>>>();
    count_both_kernel<<<(NE0 + NE1 + 255) / 256, 256>>>(e0_dst, e1_dst);
    scan_kernel<<<2, 1024>>>();
    fill_both_kernel<<<(NE0 + NE1 + 255) / 256, 256>>>(e0_src, e0_dst, e1_src, e1_dst);
    gather_mean_round_f32<IN_F><<<NDST0, IN_F / 4>>>(x, off0, eidx0, a1);

    // ---- join: GEMM1 needs prep outputs ----
    cudaStreamWaitEvent(0, evPrep, 0);

    // layer-1 dual-GEMM + bias + ReLU -> h16 (fp16, all rows)
    {
        dim3 grid(H_F / 128, (NDST0 + 127) / 128);
        sage_mma_gemm<2><<<grid, 256, SMEM1>>>(
            x16, a1, w1s, w1n, b1, nullptr, h16, NDST0, H_F, IN_F, 1);
    }
    // layer-2 gather-mean (fp16 source)
    gather_mean_round_f16<H_F><<<NDST1, H_F / 4>>>(h16, off1, eidx1, a2);
    // layer-2 dual-GEMM + bias -> out (fp32)
    {
        dim3 grid(N_CLS / 128, (NDST1 + 63) / 64);
        sage_mma_gemm<4><<<grid, 256, SMEM2>>>(
            h16, a2, w2s, w2n, b2, out, nullptr, NDST1, N_CLS, H_F, 0);
    }
}

// round 17
// speedup vs baseline: 1.0419x; 1.0419x over previous
#include <cuda_runtime.h>
#include <cuda_fp16.h>
#include <cstdint>

#define NSRC0 100000
#define NDST0 20000
#define NDST1 5000
#define NE0   160000
#define NE1   40000
#define IN_F  512
#define H_F   1024
#define N_CLS 256

#define APAD 40   // fp16 elems per smem row (32 data + 8 pad) -> 80B stride

// ---------------------------------------------------------------------------
// Scratch (device globals)
// ---------------------------------------------------------------------------
__device__ __align__(16) __half g_x16[(long long)NDST0 * IN_F];
__device__ __align__(16) __half g_a1[(long long)NDST0 * IN_F];
__device__ __align__(16) __half g_h16[(long long)NDST0 * H_F];
__device__ __align__(16) __half g_a2[(long long)NDST1 * H_F];

__device__ int g_cnt0[NDST0];
__device__ int g_off0[NDST0 + 1];
__device__ int g_cur0[NDST0];
__device__ int g_eidx0[NE0];
__device__ int g_cnt1[NDST1];
__device__ int g_off1[NDST1 + 1];
__device__ int g_cur1[NDST1];
__device__ int g_eidx1[NE1];

// fp16-rounded, pre-transposed weights: [N, K]
__device__ __align__(16) __half g_w1s[H_F * IN_F];
__device__ __align__(16) __half g_w1n[H_F * IN_F];
__device__ __align__(16) __half g_w2s[N_CLS * H_F];
__device__ __align__(16) __half g_w2n[N_CLS * H_F];

// ---------------------------------------------------------------------------
// helpers
// ---------------------------------------------------------------------------
__device__ __forceinline__ void cp16(uint32_t dst, const void* src, bool pred) {
    asm volatile("cp.async.cg.shared.global [%0], [%1], 16, %2;"
                 :: "r"(dst), "l"(src), "r"(pred ? 16 : 0));
}
__device__ __forceinline__ uint32_t pack2h(float x, float y) {
    __half hx = __float2half_rn(x);
    __half hy = __float2half_rn(y);
    return ((uint32_t)__half_as_ushort(hy) << 16) | __half_as_ushort(hx);
}
__device__ __forceinline__ void mma16816(float* c, const uint32_t* a,
                                         uint32_t b0, uint32_t b1) {
    asm volatile(
        "mma.sync.aligned.m16n8k16.row.col.f32.f16.f16.f32 "
        "{%0,%1,%2,%3}, {%4,%5,%6,%7}, {%8,%9}, {%0,%1,%2,%3};"
        : "+f"(c[0]), "+f"(c[1]), "+f"(c[2]), "+f"(c[3])
        : "r"(a[0]), "r"(a[1]), "r"(a[2]), "r"(a[3]), "r"(b0), "r"(b1));
}
#define LDSM4(r0, r1, r2, r3, addr) \
    asm volatile("ldmatrix.sync.aligned.m8n8.x4.shared.b16 {%0,%1,%2,%3}, [%4];" \
                 : "=r"(r0), "=r"(r1), "=r"(r2), "=r"(r3) : "r"(addr))

// ---------------------------------------------------------------------------
// Fused prep: 4 weight transposes (fp16 round) + x round + count zeroing.
// ---------------------------------------------------------------------------
__device__ __forceinline__ void transpose_round_body(
    const float* __restrict__ W, __half* __restrict__ dst,
    int K, int N, int n0, int k0) {
    __shared__ float t[32][33];
    int tx = threadIdx.x, ty = threadIdx.y;
#pragma unroll
    for (int i = 0; i < 4; i++)
        t[ty + 8 * i][tx] = W[(long long)(k0 + ty + 8 * i) * N + n0 + tx];
    __syncthreads();
#pragma unroll
    for (int i = 0; i < 4; i++) {
        float v = t[tx][ty + 8 * i];
        dst[(long long)(n0 + ty + 8 * i) * K + k0 + tx] = __float2half_rn(v);
    }
}

#define PREP_XSPLIT_BASE 1536
#define PREP_XSPLIT_BLKS 10000
#define PREP_ZERO_BASE   (PREP_XSPLIT_BASE + PREP_XSPLIT_BLKS)
#define PREP_ZERO_BLKS   79
#define PREP_TOTAL_BLKS  (PREP_ZERO_BASE + PREP_ZERO_BLKS)

__global__ void prep_all_kernel(const float* __restrict__ W1s, const float* __restrict__ W1n,
                                const float* __restrict__ W2s, const float* __restrict__ W2n,
                                const float* __restrict__ x) {
    int b = blockIdx.x;
    int flat = threadIdx.y * 32 + threadIdx.x;
    if (b < 1024) {
        int bb = b & 511;
        const float* W = (b < 512) ? W1s : W1n;
        __half* dst = (b < 512) ? g_w1s : g_w1n;
        transpose_round_body(W, dst, IN_F, H_F, (bb & 31) * 32, (bb >> 5) * 32);
    } else if (b < PREP_XSPLIT_BASE) {
        int bb = (b - 1024) & 255;
        const float* W = (b < 1280) ? W2s : W2n;
        __half* dst = (b < 1280) ? g_w2s : g_w2n;
        transpose_round_body(W, dst, H_F, N_CLS, (bb & 7) * 32, (bb >> 3) * 32);
    } else if (b < PREP_ZERO_BASE) {
        long long i = (long long)(b - PREP_XSPLIT_BASE) * 256 + flat;
        const long long n4 = (long long)NDST0 * IN_F / 4;
        if (i < n4) {
            float4 v = reinterpret_cast<const float4*>(x)[i];
            reinterpret_cast<uint2*>(g_x16)[i] =
                make_uint2(pack2h(v.x, v.y), pack2h(v.z, v.w));
        }
    } else {
        int i = (b - PREP_ZERO_BASE) * 256 + flat;
        if (i < NDST0) g_cnt0[i] = 0;
        if (i < NDST1) g_cnt1[i] = 0;
    }
}

// ---------------------------------------------------------------------------
// CSR build
// ---------------------------------------------------------------------------
__global__ void count_both_kernel(const int* __restrict__ e0dst,
                                  const int* __restrict__ e1dst) {
    int e = blockIdx.x * blockDim.x + threadIdx.x;
    if (e < NE0) atomicAdd(&g_cnt0[e0dst[e]], 1);
    else if (e < NE0 + NE1) atomicAdd(&g_cnt1[e1dst[e - NE0]], 1);
}

// Tiled coalesced exclusive scan: 2 blocks (one per layer), 1024 threads.
// Per 1024-tile: coalesced load, warp+smem inclusive scan, coalesced store.
__global__ void __launch_bounds__(1024) scan_kernel() {
    const int n = blockIdx.x == 0 ? NDST0 : NDST1;
    int* cnt = blockIdx.x == 0 ? g_cnt0 : g_cnt1;
    int* off = blockIdx.x == 0 ? g_off0 : g_off1;
    int* cur = blockIdx.x == 0 ? g_cur0 : g_cur1;
    __shared__ int wsum[33];   // [32] = running base
    int tid = threadIdx.x;
    int lane = tid & 31, wid = tid >> 5;
    if (tid == 0) wsum[32] = 0;
    __syncthreads();

    for (int tile = 0; tile < n; tile += 1024) {
        int i = tile + tid;
        int v = (i < n) ? cnt[i] : 0;
        int sc = v;
#pragma unroll
        for (int d = 1; d < 32; d <<= 1) {
            int u = __shfl_up_sync(0xFFFFFFFF, sc, d);
            if (lane >= d) sc += u;
        }
        if (lane == 31) wsum[wid] = sc;
        __syncthreads();                    // B1
        if (wid == 0) {
            int w = wsum[lane];
#pragma unroll
            for (int d = 1; d < 32; d <<= 1) {
                int u = __shfl_up_sync(0xFFFFFFFF, w, d);
                if (lane >= d) w += u;
            }
            wsum[lane] = w;
        }
        __syncthreads();                    // B2
        int base = wsum[32];
        int excl = base + (wid ? wsum[wid - 1] : 0) + sc - v;
        if (i < n) {
            off[i] = excl;
            cur[i] = excl;
        }
        int newbase = base + wsum[31];
        __syncthreads();                    // B3
        if (tid == 0) wsum[32] = newbase;
    }
    __syncthreads();
    if (tid == 0) off[n] = wsum[32];
}

__global__ void fill_both_kernel(const int* __restrict__ e0src, const int* __restrict__ e0dst,
                                 const int* __restrict__ e1src, const int* __restrict__ e1dst) {
    int e = blockIdx.x * blockDim.x + threadIdx.x;
    if (e < NE0) {
        int p = atomicAdd(&g_cur0[e0dst[e]], 1);
        g_eidx0[p] = e0src[e];
    } else if (e < NE0 + NE1) {
        int i = e - NE0;
        int p = atomicAdd(&g_cur1[e1dst[i]], 1);
        g_eidx1[p] = e1src[i];
    }
}

// ---------------------------------------------------------------------------
// Gather-mean + fp16 round: fp32 source (layer 1)
// ---------------------------------------------------------------------------
template <int F>
__global__ void __launch_bounds__(F / 4)
gather_mean_round_f32(const float* __restrict__ feat,
                      const int* __restrict__ off, const int* __restrict__ eidx,
                      __half* __restrict__ dst) {
    int row = blockIdx.x;
    int tid = threadIdx.x;
    int beg = off[row], end = off[row + 1];
    float4 acc = make_float4(0.f, 0.f, 0.f, 0.f);
    int j = beg;
    for (; j + 2 <= end; j += 2) {
        int s0 = eidx[j], s1 = eidx[j + 1];
        float4 v0 = reinterpret_cast<const float4*>(feat)[(long long)s0 * (F / 4) + tid];
        float4 v1 = reinterpret_cast<const float4*>(feat)[(long long)s1 * (F / 4) + tid];
        acc.x += v0.x + v1.x; acc.y += v0.y + v1.y;
        acc.z += v0.z + v1.z; acc.w += v0.w + v1.w;
    }
    if (j < end) {
        float4 v = reinterpret_cast<const float4*>(feat)[(long long)eidx[j] * (F / 4) + tid];
        acc.x += v.x; acc.y += v.y; acc.z += v.z; acc.w += v.w;
    }
    float sc = 1.0f / (float)max(end - beg, 1);
    acc.x *= sc; acc.y *= sc; acc.z *= sc; acc.w *= sc;
    long long o = (long long)row * (F / 4) + tid;
    reinterpret_cast<uint2*>(dst)[o] =
        make_uint2(pack2h(acc.x, acc.y), pack2h(acc.z, acc.w));
}

// ---------------------------------------------------------------------------
// Gather-mean + fp16 round: fp16 source (layer 2)
// ---------------------------------------------------------------------------
template <int F>
__global__ void __launch_bounds__(F / 4)
gather_mean_round_f16(const __half* __restrict__ feat,
                      const int* __restrict__ off, const int* __restrict__ eidx,
                      __half* __restrict__ dst) {
    int row = blockIdx.x;
    int tid = threadIdx.x;
    int beg = off[row], end = off[row + 1];
    float4 acc = make_float4(0.f, 0.f, 0.f, 0.f);
    int j = beg;
    for (; j + 2 <= end; j += 2) {
        int s0 = eidx[j], s1 = eidx[j + 1];
        uint2 u0 = reinterpret_cast<const uint2*>(feat)[(long long)s0 * (F / 4) + tid];
        uint2 u1 = reinterpret_cast<const uint2*>(feat)[(long long)s1 * (F / 4) + tid];
        float2 a0 = __half22float2(*reinterpret_cast<__half2*>(&u0.x));
        float2 b0 = __half22float2(*reinterpret_cast<__half2*>(&u0.y));
        float2 a1 = __half22float2(*reinterpret_cast<__half2*>(&u1.x));
        float2 b1 = __half22float2(*reinterpret_cast<__half2*>(&u1.y));
        acc.x += a0.x + a1.x; acc.y += a0.y + a1.y;
        acc.z += b0.x + b1.x; acc.w += b0.y + b1.y;
    }
    if (j < end) {
        uint2 u = reinterpret_cast<const uint2*>(feat)[(long long)eidx[j] * (F / 4) + tid];
        float2 a = __half22float2(*reinterpret_cast<__half2*>(&u.x));
        float2 b = __half22float2(*reinterpret_cast<__half2*>(&u.y));
        acc.x += a.x; acc.y += a.y; acc.z += b.x; acc.w += b.y;
    }
    float sc = 1.0f / (float)max(end - beg, 1);
    acc.x *= sc; acc.y *= sc; acc.z *= sc; acc.w *= sc;
    long long o = (long long)row * (F / 4) + tid;
    reinterpret_cast<uint2*>(dst)[o] =
        make_uint2(pack2h(acc.x, acc.y), pack2h(acc.z, acc.w));
}

// ---------------------------------------------------------------------------
// 2-stage BK=32 pipelined dual-pair plain-fp16 GEMM:
//   C/C16 = act( A0 @ B0^T + A1 @ B1^T + bias )
// ---------------------------------------------------------------------------
template <int NW_N>
__global__ void __launch_bounds__(256, 2)
sage_mma_gemm(const __half* __restrict__ A0, const __half* __restrict__ A1,
              const __half* __restrict__ B0, const __half* __restrict__ B1,
              const float* __restrict__ bias, float* __restrict__ C,
              __half* __restrict__ C16,
              int M, int N, int K, int doRelu) {
    constexpr int BM = 32 * (8 / NW_N);      // 128 | 64
    constexpr int NJ = 128 / (8 * NW_N);     // 8 | 4
    constexpr int NA = BM / 64;              // 2 | 1
    constexpr int ATILE = BM * APAD;
    constexpr int BTILE = 128 * APAD;
    constexpr int SSTRIDE = ATILE + BTILE;

    extern __shared__ __half sm[];
    uint32_t sbase = (uint32_t)__cvta_generic_to_shared(sm);

    int tid = threadIdx.x;
    int wid = tid >> 5;
    int lane = tid & 31;
    int g = lane >> 2;
    int t = lane & 3;
    int warpM = wid / NW_N;
    int warpN = wid % NW_N;
    int rowC = blockIdx.y * BM;
    int colC = blockIdx.x * 128;

    const uint32_t offA = ((uint32_t)(((lane & 15) + warpM * 32) * APAD
                          + ((lane >> 4) << 3))) * 2;
    const uint32_t offBl = ((uint32_t)((((lane >> 4) << 3) + (lane & 7)) * APAD
                          + (((lane >> 3) & 1) << 3))) * 2;

    long long offAg[NA];
    uint32_t  smA[NA];
    bool      pv[NA];
#pragma unroll
    for (int it = 0; it < NA; it++) {
        int u = tid + it * 256;
        int r = u >> 2, c = u & 3;
        int gr = rowC + r;
        pv[it] = gr < M;
        offAg[it] = (long long)(pv[it] ? gr : 0) * K + (c << 3);
        smA[it] = (uint32_t)(r * APAD + (c << 3)) * 2;
    }
    long long offBg[2];
    uint32_t  smB[2];
#pragma unroll
    for (int it = 0; it < 2; it++) {
        int u = tid + it * 256;
        int r = u >> 2, c = u & 3;
        offBg[it] = (long long)(colC + r) * K + (c << 3);
        smB[it] = (uint32_t)(r * APAD + (c << 3)) * 2;
    }

    const int nk = K >> 5;
    const int total = 2 * nk;

    auto issue = [&](int q, int s) {
        int pass = q >= nk;
        int k0 = (pass ? q - nk : q) << 5;
        const __half* Ap = pass ? A1 : A0;
        const __half* Bp = pass ? B1 : B0;
        uint32_t sb = sbase + (uint32_t)s * (SSTRIDE * 2);
#pragma unroll
        for (int it = 0; it < NA; it++)
            cp16(sb + smA[it], Ap + offAg[it] + k0, pv[it]);
#pragma unroll
        for (int it = 0; it < 2; it++)
            cp16(sb + ATILE * 2 + smB[it], Bp + offBg[it] + k0, true);
        asm volatile("cp.async.commit_group;" ::: "memory");
    };

    float acc[2][NJ][4];
#pragma unroll
    for (int i = 0; i < 2; i++)
#pragma unroll
        for (int j = 0; j < NJ; j++)
#pragma unroll
            for (int q = 0; q < 4; q++) acc[i][j][q] = 0.0f;

    issue(0, 0);

#pragma unroll 1
    for (int q = 0; q < total; q++) {
        int s = q & 1;
        if (q + 1 < total) {
            issue(q + 1, s ^ 1);
            asm volatile("cp.async.wait_group 1;" ::: "memory");
        } else {
            asm volatile("cp.async.wait_group 0;" ::: "memory");
        }
        __syncthreads();

        uint32_t baseA = sbase + (uint32_t)s * (SSTRIDE * 2);
        uint32_t baseB = baseA + ATILE * 2;

#pragma unroll
        for (int ks = 0; ks < 2; ks++) {
            uint32_t kof = (uint32_t)ks * 32;
            uint32_t ah[2][4];
#pragma unroll
            for (int i = 0; i < 2; i++)
                LDSM4(ah[i][0], ah[i][1], ah[i][2], ah[i][3],
                      baseA + offA + (uint32_t)(i * 16 * APAD) * 2 + kof);
            uint32_t b[NJ][2];
#pragma unroll
            for (int j2 = 0; j2 < NJ / 2; j2++) {
                uint32_t nbo = (uint32_t)((warpN * (NJ * 8) + j2 * 16) * APAD) * 2;
                LDSM4(b[2 * j2][0], b[2 * j2][1], b[2 * j2 + 1][0], b[2 * j2 + 1][1],
                      baseB + offBl + nbo + kof);
            }
#pragma unroll
            for (int i = 0; i < 2; i++)
#pragma unroll
                for (int j = 0; j < NJ; j++)
                    mma16816(acc[i][j], ah[i], b[j][0], b[j][1]);
        }
        __syncthreads();
    }

    // epilogue
#pragma unroll
    for (int i = 0; i < 2; i++) {
#pragma unroll
        for (int j = 0; j < NJ; j++) {
            int row = rowC + warpM * 32 + i * 16 + g;
            int col = colC + warpN * (NJ * 8) + j * 8 + 2 * t;
            float bx = bias[col], by = bias[col + 1];
            float2 v0, v1;
            v0.x = acc[i][j][0] + bx; v0.y = acc[i][j][1] + by;
            v1.x = acc[i][j][2] + bx; v1.y = acc[i][j][3] + by;
            if (doRelu) {
                v0.x = fmaxf(v0.x, 0.f); v0.y = fmaxf(v0.y, 0.f);
                v1.x = fmaxf(v1.x, 0.f); v1.y = fmaxf(v1.y, 0.f);
            }
            if (C) {
                if (row < M)
                    *reinterpret_cast<float2*>(C + (long long)row * N + col) = v0;
                if (row + 8 < M)
                    *reinterpret_cast<float2*>(C + (long long)(row + 8) * N + col) = v1;
            }
            if (C16) {
                if (row < M)
                    *reinterpret_cast<uint32_t*>(C16 + (long long)row * N + col) =
                        pack2h(v0.x, v0.y);
                if (row + 8 < M)
                    *reinterpret_cast<uint32_t*>(C16 + (long long)(row + 8) * N + col) =
                        pack2h(v1.x, v1.y);
            }
        }
    }
}

// ---------------------------------------------------------------------------
extern "C" void kernel_launch(void* const* d_in, const int* in_sizes, int n_in,
                              void* d_out, int out_size) {
    const float* x        = (const float*)d_in[0];
    const float* W_self1  = (const float*)d_in[1];
    const float* W_neigh1 = (const float*)d_in[2];
    const float* b1       = (const float*)d_in[3];
    const float* W_self2  = (const float*)d_in[4];
    const float* W_neigh2 = (const float*)d_in[5];
    const float* b2       = (const float*)d_in[6];
    const int*   e0_src   = (const int*)d_in[7];
    const int*   e0_dst   = (const int*)d_in[8];
    const int*   e1_src   = (const int*)d_in[9];
    const int*   e1_dst   = (const int*)d_in[10];
    float* out = (float*)d_out;

    __half *x16, *a1, *h16, *a2;
    cudaGetSymbolAddress((void**)&x16, g_x16);
    cudaGetSymbolAddress((void**)&a1,  g_a1);
    cudaGetSymbolAddress((void**)&h16, g_h16);
    cudaGetSymbolAddress((void**)&a2,  g_a2);
    __half *w1s, *w1n, *w2s, *w2n;
    cudaGetSymbolAddress((void**)&w1s, g_w1s);
    cudaGetSymbolAddress((void**)&w1n, g_w1n);
    cudaGetSymbolAddress((void**)&w2s, g_w2s);
    cudaGetSymbolAddress((void**)&w2n, g_w2n);
    int *off0, *eidx0, *off1, *eidx1;
    cudaGetSymbolAddress((void**)&off0, g_off0);
    cudaGetSymbolAddress((void**)&eidx0, g_eidx0);
    cudaGetSymbolAddress((void**)&off1, g_off1);
    cudaGetSymbolAddress((void**)&eidx1, g_eidx1);

    constexpr int SMEM1 = 2 * ((128 + 128) * APAD * 2);  // 40960B
    constexpr int SMEM2 = 2 * ((64 + 128) * APAD * 2);   // 30720B
    static bool attr_set = false;
    if (!attr_set) {
        cudaFuncSetAttribute(sage_mma_gemm<2>, cudaFuncAttributeMaxDynamicSharedMemorySize, SMEM1);
        cudaFuncSetAttribute(sage_mma_gemm<4>, cudaFuncAttributeMaxDynamicSharedMemorySize, SMEM2);
        attr_set = true;
    }

    // 1. fused prep (weights + x16 + count zeroing)
    prep_all_kernel<<<PREP_TOTAL_BLKS, dim3(32, 8)>>>(W_self1, W_neigh1, W_self2, W_neigh2, x);
    // 2-4. CSR build
    count_both_kernel<<<(NE0 + NE1 + 255) / 256, 256>>>(e0_dst, e1_dst);
    scan_kernel<<<2, 1024>>>();
    fill_both_kernel<<<(NE0 + NE1 + 255) / 256, 256>>>(e0_src, e0_dst, e1_src, e1_dst);
    // 5. layer-1 gather-mean (fp32 x source)
    gather_mean_round_f32<IN_F><<<NDST0, IN_F / 4>>>(x, off0, eidx0, a1);
    // 6. layer-1 dual-GEMM + bias + ReLU -> h16 (fp16, all rows)
    {
        dim3 grid(H_F / 128, (NDST0 + 127) / 128);
        sage_mma_gemm<2><<<grid, 256, SMEM1>>>(
            x16, a1, w1s, w1n, b1, nullptr, h16, NDST0, H_F, IN_F, 1);
    }
    // 7. layer-2 gather-mean (fp16 source)
    gather_mean_round_f16<H_F><<<NDST1, H_F / 4>>>(h16, off1, eidx1, a2);
    // 8. layer-2 dual-GEMM + bias -> out (fp32)
    {
        dim3 grid(N_CLS / 128, (NDST1 + 63) / 64);
        sage_mma_gemm<4><<<grid, 256, SMEM2>>>(
            h16, a2, w2s, w2n, b2, out, nullptr, NDST1, N_CLS, H_F, 0);
    }
}